// round 6
// baseline (speedup 1.0000x reference)
#include <cuda_runtime.h>

// ---------------------------------------------------------------------------
// RobustStateSpaceSimulatorAugmented: B=1024 rows, T=256 sequential steps.
// Parallel over batch only: 128 CTAs x 512 threads, 8 rows per CTA, rows
// packed in pairs into f32x2 lanes for fma.rn.f32x2 (Blackwell FFMA2).
//
// Numerics: pure fp32, mirroring XLA/JAX per-op arithmetic:
//  - tanh = XLA's EmitFastTanh rational approximation (Eigen ptanh),
//  - every dot product is a single ascending-k fp32 FMA chain (canonical
//    GEMM microkernel accumulation order), bias added after the dot,
//  - elementwise gate / mu / sigma math follows the reference expression
//    tree op-for-op (IEEE correctly-rounded ops => bitwise reproducible).
// ---------------------------------------------------------------------------

namespace {
constexpr int B_  = 1024;
constexpr int T_  = 256;
constexpr int NXF_ = 64;
constexpr int NXB_ = 32;
constexpr int NU_  = 16;
constexpr int NY_  = 16;
constexpr int NTH_ = 8;
constexpr int HID_ = 512;

constexpr int BM = 8;        // batch rows per CTA
constexpr int P  = BM / 2;   // row pairs (f32x2 lanes)
constexpr int NT = 512;      // threads per CTA

constexpr int DIN_F  = NXF_ + NU_  + NTH_;  // 88
constexpr int DIN_FB = NXF_ + NXB_ + NU_;   // 112
constexpr int DIN_H  = NXF_ + NTH_;         // 72
constexpr int DIN_HB = NXF_ + NXB_;         // 96
constexpr int DIN_MAX = 112;

// output packing: reference returns (x_f, x_b, y, x_p)
constexpr long OFF_XF = 0;
constexpr long OFF_XB = OFF_XF + (long)B_ * T_ * NXF_;
constexpr long OFF_Y  = OFF_XB + (long)B_ * T_ * NXB_;
constexpr long OFF_XP = OFF_Y  + (long)B_ * T_ * NY_;
} // namespace

// ---------------------------------------------------------------------------
// f32x2 helpers (Blackwell packed fp32 FMA)
// ---------------------------------------------------------------------------
__device__ __forceinline__ unsigned long long pack2(float w) {
    unsigned long long r;
    asm("mov.b64 %0, {%1, %1};" : "=l"(r) : "f"(w));
    return r;
}

__device__ __forceinline__ float2 unpack2(unsigned long long v) {
    float2 r;
    asm("mov.b64 {%0, %1}, %2;" : "=f"(r.x), "=f"(r.y) : "l"(v));
    return r;
}

__device__ __forceinline__ void ffma2(unsigned long long& acc,
                                      unsigned long long a,
                                      unsigned long long b) {
    asm("fma.rn.f32x2 %0, %1, %2, %0;" : "+l"(acc) : "l"(a), "l"(b));
}

__device__ __forceinline__ float clipf(float v, float lo, float hi) {
    return fminf(fmaxf(v, lo), hi);
}

// XLA f32 tanh: EmitFastTanh rational approximation (Eigen ptanh), with the
// |x| < 0.0004 identity shortcut used by ElementalIrEmitter::EmitTanh.
__device__ __forceinline__ float xla_tanh(float x) {
    const float kMax = 7.90531110763549805f;
    float xc = fminf(fmaxf(x, -kMax), kMax);
    float x2 = xc * xc;
    float n = -2.76076847742355e-16f;
    n = fmaf(x2, n,  2.00018790482477e-13f);
    n = fmaf(x2, n, -8.60467152213735e-11f);
    n = fmaf(x2, n,  5.12229709037114e-08f);
    n = fmaf(x2, n,  1.48572235717979e-05f);
    n = fmaf(x2, n,  6.37261928875436e-04f);
    n = fmaf(x2, n,  4.89352455891786e-03f);
    n = xc * n;
    float d = 1.19825839466702e-06f;
    d = fmaf(x2, d, 1.18534705686654e-04f);
    d = fmaf(x2, d, 2.26843463243900e-03f);
    d = fmaf(x2, d, 4.89352518554385e-03f);
    float r = n / d;
    return fabsf(x) < 0.0004f ? x : r;
}

// ---------------------------------------------------------------------------
// shared memory layout (per CTA); pair-packed: elem (p,i) holds rows 2p,2p+1
// ---------------------------------------------------------------------------
struct __align__(16) Smem {
    float2 in2[DIN_MAX * P];   // layer-1 input, layout [k][p] (for LDS.128)
    float2 hid2[P * HID_];     // hidden acts, layout [p][k] (bcast in layer-2)
    float2 xp[P * NXF_];
    float2 xf[P * NXF_];
    float2 xb[P * NXB_];
    float2 mu[P * NXB_];
    float2 sig[P * NXB_];
    float2 uu[P * NU_];
    float2 thf[P * NTH_];
    float2 thh[P * NTH_];
    float2 fo[P * NXF_];
    float2 fbo[P * NXF_];
    float2 gbo[P * NXB_];
    float2 yo[P * NY_];
};

// build concatenated layer-1 input [k][p] from up to 3 pair-packed segments
__device__ __forceinline__ void build3(Smem& sm, int tid, int din,
                                       const float2* A, int lenA,
                                       const float2* Bp, int lenB,
                                       const float2* C, int lenC) {
    int total = din * P;
    if (tid < total) {
        int p = tid / din;
        int k = tid - p * din;
        float2 v;
        if (k < lenA)              v = A[p * lenA + k];
        else if (k < lenA + lenB)  v = Bp[p * lenB + (k - lenA)];
        else                       v = C[p * lenC + (k - lenA - lenB)];
        sm.in2[(k << 2) | p] = v;
    }
}

// layer 1: thread j owns hidden unit j for all 8 rows (4 f32x2 accumulators).
// Single ascending-k FMA chain per accumulator; bias added after the dot.
__device__ __forceinline__ void layer1(const float* __restrict__ W1,
                                       const float* __restrict__ b1,
                                       int din, Smem& sm, int j) {
    unsigned long long a0 = 0ull, a1 = 0ull, a2 = 0ull, a3 = 0ull;
    const ulonglong2* in = reinterpret_cast<const ulonglong2*>(sm.in2);
    const float* Wp = W1 + j;
#pragma unroll 4
    for (int k = 0; k < din; k++) {
        unsigned long long ww = pack2(__ldg(Wp));
        Wp += HID_;
        ulonglong2 q01 = in[2 * k];
        ulonglong2 q23 = in[2 * k + 1];
        ffma2(a0, ww, q01.x);
        ffma2(a1, ww, q01.y);
        ffma2(a2, ww, q23.x);
        ffma2(a3, ww, q23.y);
    }
    float bb = __ldg(b1 + j);
    float2 v;
    v = unpack2(a0);
    sm.hid2[0 * HID_ + j] = make_float2(xla_tanh(v.x + bb), xla_tanh(v.y + bb));
    v = unpack2(a1);
    sm.hid2[1 * HID_ + j] = make_float2(xla_tanh(v.x + bb), xla_tanh(v.y + bb));
    v = unpack2(a2);
    sm.hid2[2 * HID_ + j] = make_float2(xla_tanh(v.x + bb), xla_tanh(v.y + bb));
    v = unpack2(a3);
    sm.hid2[3 * HID_ + j] = make_float2(xla_tanh(v.x + bb), xla_tanh(v.y + bb));
}

// layer 2: one thread per (output j, row-pair p); SINGLE ascending-k FMA
// chain over the full K=512 (canonical GEMM accumulation order).
// tid = p*DOUT + j so W2 loads are warp-coalesced, hid2 reads broadcast.
template <int DOUT, bool ACC>
__device__ __forceinline__ void layer2(const float* __restrict__ W2,
                                       const float* __restrict__ b2,
                                       Smem& sm, float2* __restrict__ outv,
                                       int tid) {
    if (tid < DOUT * P) {
        const int j = tid % DOUT;
        const int p = tid / DOUT;
        const unsigned long long* hp =
            reinterpret_cast<const unsigned long long*>(sm.hid2) + p * HID_;
        const float* Wp = W2 + j;
        unsigned long long acc = 0ull;
#pragma unroll 8
        for (int k = 0; k < HID_; k++) {
            ffma2(acc, pack2(__ldg(Wp)), hp[k]);
            Wp += DOUT;
        }
        float2 s = unpack2(acc);
        float bb = __ldg(b2 + j);
        s.x += bb; s.y += bb;
        if (ACC) { float2 o = outv[tid]; s.x += o.x; s.y += o.y; }
        outv[tid] = s;
    }
    __syncthreads();
}

// robust gating + mu/sigma update — expression ordering mirrors the JAX code
__device__ __forceinline__ void gate_update(float xb, float mu, float sig, float gbv,
                                            float t1, float t2, float xblo, float xbhi,
                                            float& xbn, float& mun, float& sgn) {
    // gamma_plus = sig ** 1
    float inv_gp  = 1.0f / sig;
    float inv_gp2 = 1.0f / (sig * sig);
    float xmmu = xb - mu;
    float delta1 = gbv * (xmmu + (gbv * 0.5f) * (1.0f + inv_gp));
    float delta2 = 1.0f - inv_gp;
    float delta = delta1 * delta2;
    float eps = t2 * (sig * sig - t2 / t1)
              + xmmu * (xmmu + gbv * (1.0f + inv_gp)
                        + (gbv * gbv * 0.5f) * (1.0f + inv_gp2));
    float d2e2 = delta * delta - eps * eps;
    bool c = ((eps >= delta) && (delta >= 0.0f))
          || ((eps <  delta) && (delta <  0.0f))
          || ((delta < eps)  && (eps  <  0.0f))
          || (((2.0f * t2 * t2 / t1) * eps >= d2e2) && (d2e2 > 0.0f));
    float gamma = c ? sig : 1.0f;
    float dxb = gbv / gamma;
    xbn = dxb;                                // unclipped (used by h_b)
    float xbc = fminf(fmaxf(dxb, xblo), xbhi);
    float c1 = t1 / t2;
    float c2 = 1.0f / t2;
    mun = c1 * mu + c2 * xbc;
    float dm = xbc - mun;
    sgn = sqrtf(c1 * (sig * sig) + c2 * (dm * dm));
}

// store (and optionally clip + write back) one time-index of outputs
__device__ __forceinline__ void store_outputs(float* __restrict__ out, Smem& sm,
                                              int b0, int ti, int tid, bool doclip,
                                              float xlo, float xhi, float xblo,
                                              float xbhi, float ylo, float yhi) {
    float* sxf = reinterpret_cast<float*>(sm.xf);
    float* sxp = reinterpret_cast<float*>(sm.xp);
    float* sxb = reinterpret_cast<float*>(sm.xb);
    float* sy  = reinterpret_cast<float*>(sm.yo);
    {
        int bm = tid >> 6, i = tid & 63;
        int si = (((bm >> 1) * NXF_ + i) << 1) | (bm & 1);
        size_t base = ((size_t)(b0 + bm) * T_ + ti);
        float vf = sxf[si], vp = sxp[si];
        if (doclip) {
            vf = clipf(vf, xlo, xhi); vp = clipf(vp, xlo, xhi);
            sxf[si] = vf; sxp[si] = vp;
        }
        out[OFF_XF + base * NXF_ + i] = vf;
        out[OFF_XP + base * NXF_ + i] = vp;
    }
    if (tid < 256) {
        int bm = tid >> 5, i = tid & 31;
        int si = (((bm >> 1) * NXB_ + i) << 1) | (bm & 1);
        float v = sxb[si];
        if (doclip) { v = clipf(v, xblo, xbhi); sxb[si] = v; }
        out[OFF_XB + ((size_t)(b0 + bm) * T_ + ti) * NXB_ + i] = v;
    }
    if (tid < 128) {
        int bm = tid >> 4, i = tid & 15;
        int si = (((bm >> 1) * NY_ + i) << 1) | (bm & 1);
        float v = sy[si];
        if (doclip) v = clipf(v, ylo, yhi);
        out[OFF_Y + ((size_t)(b0 + bm) * T_ + ti) * NY_ + i] = v;
    }
}

// ---------------------------------------------------------------------------
// main persistent kernel: one CTA simulates 8 batch rows for all 256 steps
// ---------------------------------------------------------------------------
__global__ void __launch_bounds__(NT, 1)
sim_kernel(const float* __restrict__ xf0, const float* __restrict__ xb0,
           const float* __restrict__ u,   const float* __restrict__ thfg,
           const float* __restrict__ thhg,
           const float* __restrict__ fW1,  const float* __restrict__ fb1,
           const float* __restrict__ fW2,  const float* __restrict__ fb2_,
           const float* __restrict__ fbW1, const float* __restrict__ fbb1,
           const float* __restrict__ fbW2, const float* __restrict__ fbb2,
           const float* __restrict__ gbW1, const float* __restrict__ gbb1,
           const float* __restrict__ gbW2, const float* __restrict__ gbb2,
           const float* __restrict__ hW1,  const float* __restrict__ hb1,
           const float* __restrict__ hW2,  const float* __restrict__ hb2_,
           const float* __restrict__ hbW1, const float* __restrict__ hbb1,
           const float* __restrict__ hbW2, const float* __restrict__ hbb2,
           const float* __restrict__ pxlo, const float* __restrict__ pxhi,
           const float* __restrict__ pxblo,const float* __restrict__ pxbhi,
           const float* __restrict__ pylo, const float* __restrict__ pyhi,
           float* __restrict__ out) {
    __shared__ Smem sm;
    const int tid = threadIdx.x;
    const int b0  = blockIdx.x * BM;
    const float xlo = pxlo[0], xhi = pxhi[0];
    const float xblo = pxblo[0], xbhi = pxbhi[0];
    const float ylo = pylo[0], yhi = pyhi[0];

    // ---- prologue: load initial state (pair-packed) ----
    {
        int bm = tid >> 6, i = tid & 63;
        float v = xf0[(b0 + bm) * NXF_ + i];
        int si = (((bm >> 1) * NXF_ + i) << 1) | (bm & 1);
        reinterpret_cast<float*>(sm.xf)[si] = v;
        reinterpret_cast<float*>(sm.xp)[si] = v;
    }
    if (tid < 256) {
        int bm = tid >> 5, i = tid & 31;
        float v = xb0[(b0 + bm) * NXB_ + i];
        int si = (((bm >> 1) * NXB_ + i) << 1) | (bm & 1);
        reinterpret_cast<float*>(sm.xb)[si]  = v;
        reinterpret_cast<float*>(sm.mu)[si]  = 0.0f;
        reinterpret_cast<float*>(sm.sig)[si] = 1.0f;
    }
    if (tid < 64) {
        int bm = tid >> 3, i = tid & 7;
        int si = (((bm >> 1) * NTH_ + i) << 1) | (bm & 1);
        reinterpret_cast<float*>(sm.thf)[si] = thfg[(b0 + bm) * NTH_ + i];
        reinterpret_cast<float*>(sm.thh)[si] = thhg[(b0 + bm) * NTH_ + i];
    }
    __syncthreads();

    // ---- y0 = h(x_f_0) + h_b(x_f_0, x_b_0), stored (unclipped) at t=0 ----
    build3(sm, tid, DIN_H, sm.xp, NXF_, sm.thh, NTH_, sm.thh, 0);
    __syncthreads();
    layer1(hW1, hb1, DIN_H, sm, tid);
    __syncthreads();
    layer2<NY_, false>(hW2, hb2_, sm, sm.yo, tid);
    build3(sm, tid, DIN_HB, sm.xf, NXF_, sm.xb, NXB_, sm.xb, 0);
    __syncthreads();
    layer1(hbW1, hbb1, DIN_HB, sm, tid);
    __syncthreads();
    layer2<NY_, true>(hbW2, hbb2, sm, sm.yo, tid);

    store_outputs(out, sm, b0, 0, tid, false, xlo, xhi, xblo, xbhi, ylo, yhi);
    __syncthreads();

    // ---- main recurrence: updates for t = 0..254, stored at t+1 ----
    for (int t = 0; t < T_ - 1; t++) {
        const float tf = (float)t;

        if (tid < BM * NU_) {   // load u[:, t, :]
            int bm = tid >> 4, i = tid & 15;
            reinterpret_cast<float*>(sm.uu)[(((bm >> 1) * NU_ + i) << 1) | (bm & 1)] =
                u[((size_t)(b0 + bm) * T_ + t) * NU_ + i];
        }
        __syncthreads();

        // f(xp, u, theta_f)
        build3(sm, tid, DIN_F, sm.xp, NXF_, sm.uu, NU_, sm.thf, NTH_);
        __syncthreads();
        layer1(fW1, fb1, DIN_F, sm, tid);
        __syncthreads();
        layer2<NXF_, false>(fW2, fb2_, sm, sm.fo, tid);

        // f_b and g_b share the concat (xp, xb, u)
        build3(sm, tid, DIN_FB, sm.xp, NXF_, sm.xb, NXB_, sm.uu, NU_);
        __syncthreads();
        layer1(fbW1, fbb1, DIN_FB, sm, tid);
        __syncthreads();
        layer2<NXF_, false>(fbW2, fbb2, sm, sm.fbo, tid);
        layer1(gbW1, gbb1, DIN_FB, sm, tid);
        __syncthreads();
        layer2<NXB_, false>(gbW2, gbb2, sm, sm.gbo, tid);

        // elementwise state update (unclipped values kept for h / h_b)
        if (tid < 128) {                       // gating on xb (32 dims x 4 pairs)
            int q = tid;
            float2 xb2 = sm.xb[q], mu2 = sm.mu[q], sg2 = sm.sig[q], gb2 = sm.gbo[q];
            float xbn, mun, sgn;
            gate_update(xb2.x, mu2.x, sg2.x, gb2.x, tf + 1.0f, tf + 2.0f,
                        xblo, xbhi, xbn, mun, sgn);
            xb2.x = xbn; mu2.x = mun; sg2.x = sgn;
            gate_update(xb2.y, mu2.y, sg2.y, gb2.y, tf + 1.0f, tf + 2.0f,
                        xblo, xbhi, xbn, mun, sgn);
            xb2.y = xbn; mu2.y = mun; sg2.y = sgn;
            sm.xb[q] = xb2; sm.mu[q] = mu2; sm.sig[q] = sg2;
        } else if (tid < 384) {                // xp_n, xf_n (64 dims x 4 pairs)
            int q = tid - 128;
            float2 xp2 = sm.xp[q], xf2 = sm.xf[q], f2 = sm.fo[q], fb2 = sm.fbo[q];
            float dfx = f2.x + fb2.x, dfy = f2.y + fb2.y;
            sm.xp[q] = make_float2(xp2.x + f2.x, xp2.y + f2.y);
            sm.xf[q] = make_float2(xf2.x + dfx, xf2.y + dfy);
        }
        __syncthreads();

        // y_n = h(xp_n) + h_b(xf_n, xb_n)   (pre-clip values, as in reference)
        build3(sm, tid, DIN_H, sm.xp, NXF_, sm.thh, NTH_, sm.thh, 0);
        __syncthreads();
        layer1(hW1, hb1, DIN_H, sm, tid);
        __syncthreads();
        layer2<NY_, false>(hW2, hb2_, sm, sm.yo, tid);
        build3(sm, tid, DIN_HB, sm.xf, NXF_, sm.xb, NXB_, sm.xb, 0);
        __syncthreads();
        layer1(hbW1, hbb1, DIN_HB, sm, tid);
        __syncthreads();
        layer2<NY_, true>(hbW2, hbb2, sm, sm.yo, tid);

        // clip states (write-back) + store outputs at t+1
        store_outputs(out, sm, b0, t + 1, tid, true, xlo, xhi, xblo, xbhi, ylo, yhi);
        __syncthreads();
    }
}

// ---------------------------------------------------------------------------
extern "C" void kernel_launch(void* const* d_in, const int* in_sizes, int n_in,
                              void* d_out, int out_size) {
    (void)in_sizes; (void)n_in; (void)out_size;
    const float* a0  = (const float*)d_in[0];   // x_f_0
    const float* a1  = (const float*)d_in[1];   // x_b_0
    const float* a2  = (const float*)d_in[2];   // u
    const float* a3  = (const float*)d_in[3];   // theta_f
    const float* a4  = (const float*)d_in[4];   // theta_h
    const float* a5  = (const float*)d_in[5];   // f_W1
    const float* a6  = (const float*)d_in[6];
    const float* a7  = (const float*)d_in[7];
    const float* a8  = (const float*)d_in[8];
    const float* a9  = (const float*)d_in[9];   // fb_W1
    const float* a10 = (const float*)d_in[10];
    const float* a11 = (const float*)d_in[11];
    const float* a12 = (const float*)d_in[12];
    const float* a13 = (const float*)d_in[13];  // gb_W1
    const float* a14 = (const float*)d_in[14];
    const float* a15 = (const float*)d_in[15];
    const float* a16 = (const float*)d_in[16];
    const float* a17 = (const float*)d_in[17];  // h_W1
    const float* a18 = (const float*)d_in[18];
    const float* a19 = (const float*)d_in[19];
    const float* a20 = (const float*)d_in[20];
    const float* a21 = (const float*)d_in[21];  // hb_W1
    const float* a22 = (const float*)d_in[22];
    const float* a23 = (const float*)d_in[23];
    const float* a24 = (const float*)d_in[24];
    const float* a25 = (const float*)d_in[25];  // x_lo
    const float* a26 = (const float*)d_in[26];  // x_hi
    const float* a27 = (const float*)d_in[27];  // xb_lo
    const float* a28 = (const float*)d_in[28];  // xb_hi
    const float* a29 = (const float*)d_in[29];  // y_lo
    const float* a30 = (const float*)d_in[30];  // y_hi

    sim_kernel<<<B_ / BM, NT>>>(a0, a1, a2, a3, a4,
                                a5, a6, a7, a8,
                                a9, a10, a11, a12,
                                a13, a14, a15, a16,
                                a17, a18, a19, a20,
                                a21, a22, a23, a24,
                                a25, a26, a27, a28, a29, a30,
                                (float*)d_out);
}

// round 7
// speedup vs baseline: 1.4729x; 1.4729x over previous
#include <cuda_runtime.h>

// ---------------------------------------------------------------------------
// RobustStateSpaceSimulatorAugmented: B=1024 rows, T=256 sequential steps.
// 128 CTAs x 512 threads, 8 rows per CTA, rows packed in pairs into f32x2.
//
// Numerics FROZEN (passing config): XLA EmitFastTanh, every dot product is a
// single ascending-k fp32x2 FMA chain, bias after dot, gate math op-for-op.
// This round only changes SCHEDULING: f/fb/gb fused (12 chains/thread in L1,
// fused L2 with dual-chain threads), h/hb fused, 8 barriers/step, u prefetch.
// ---------------------------------------------------------------------------

namespace {
constexpr int B_  = 1024;
constexpr int T_  = 256;
constexpr int NXF_ = 64;
constexpr int NXB_ = 32;
constexpr int NU_  = 16;
constexpr int NY_  = 16;
constexpr int NTH_ = 8;
constexpr int HID_ = 512;

constexpr int BM = 8;        // batch rows per CTA
constexpr int P  = BM / 2;   // row pairs (f32x2 lanes)
constexpr int NT = 512;      // threads per CTA

constexpr int DIN_F  = NXF_ + NU_  + NTH_;  // 88
constexpr int DIN_FB = NXF_ + NXB_ + NU_;   // 112
constexpr int DIN_H  = NXF_ + NTH_;         // 72
constexpr int DIN_HB = NXF_ + NXB_;         // 96

// output packing: reference returns (x_f, x_b, y, x_p)
constexpr long OFF_XF = 0;
constexpr long OFF_XB = OFF_XF + (long)B_ * T_ * NXF_;
constexpr long OFF_Y  = OFF_XB + (long)B_ * T_ * NXB_;
constexpr long OFF_XP = OFF_Y  + (long)B_ * T_ * NY_;
} // namespace

typedef unsigned long long ull;

// ---------------------------------------------------------------------------
// f32x2 helpers (Blackwell packed fp32 FMA)
// ---------------------------------------------------------------------------
__device__ __forceinline__ ull pack2(float w) {
    ull r;
    asm("mov.b64 %0, {%1, %1};" : "=l"(r) : "f"(w));
    return r;
}

__device__ __forceinline__ float2 unpack2(ull v) {
    float2 r;
    asm("mov.b64 {%0, %1}, %2;" : "=f"(r.x), "=f"(r.y) : "l"(v));
    return r;
}

__device__ __forceinline__ void ffma2(ull& acc, ull a, ull b) {
    asm("fma.rn.f32x2 %0, %1, %2, %0;" : "+l"(acc) : "l"(a), "l"(b));
}

__device__ __forceinline__ float clipf(float v, float lo, float hi) {
    return fminf(fmaxf(v, lo), hi);
}

// XLA f32 tanh: EmitFastTanh rational approximation (Eigen ptanh), with the
// |x| < 0.0004 identity shortcut used by ElementalIrEmitter::EmitTanh.
__device__ __forceinline__ float xla_tanh(float x) {
    const float kMax = 7.90531110763549805f;
    float xc = fminf(fmaxf(x, -kMax), kMax);
    float x2 = xc * xc;
    float n = -2.76076847742355e-16f;
    n = fmaf(x2, n,  2.00018790482477e-13f);
    n = fmaf(x2, n, -8.60467152213735e-11f);
    n = fmaf(x2, n,  5.12229709037114e-08f);
    n = fmaf(x2, n,  1.48572235717979e-05f);
    n = fmaf(x2, n,  6.37261928875436e-04f);
    n = fmaf(x2, n,  4.89352455891786e-03f);
    n = xc * n;
    float d = 1.19825839466702e-06f;
    d = fmaf(x2, d, 1.18534705686654e-04f);
    d = fmaf(x2, d, 2.26843463243900e-03f);
    d = fmaf(x2, d, 4.89352518554385e-03f);
    float r = n / d;
    return fabsf(x) < 0.0004f ? x : r;
}

__device__ __forceinline__ float2 tanh2(ull acc, float bb) {
    float2 v = unpack2(acc);
    return make_float2(xla_tanh(v.x + bb), xla_tanh(v.y + bb));
}

// ---------------------------------------------------------------------------
// dynamic shared memory layout (~74 KB)
// ---------------------------------------------------------------------------
struct __align__(16) SmemX {
    float2 in_f [DIN_F  * P];  // layer-1 inputs, layout [k][p]
    float2 in_fb[DIN_FB * P];
    float2 in_h [DIN_H  * P];
    float2 in_hb[DIN_HB * P];
    float2 hidf [P * HID_];    // f hidden (reused as h hidden)
    float2 hidfb[P * HID_];    // fb hidden (reused as hb hidden)
    float2 hidgb[P * HID_];    // gb hidden
    float2 xp[P * NXF_], xf[P * NXF_];
    float2 xb[P * NXB_], mu[P * NXB_], sig[P * NXB_];
    float2 uu[P * NU_], thf[P * NTH_], thh[P * NTH_];
    float2 fo[P * NXF_], fbo[P * NXF_], gbo[P * NXB_];
    float2 yoh[P * NY_], yohb[P * NY_];
};

// ---------------------------------------------------------------------------
// layer-2 dots: SINGLE ascending-k chain per output (numerics frozen)
// ---------------------------------------------------------------------------
template <int DOUT>
__device__ __forceinline__ float2 dot512(const float* __restrict__ W2,
                                         const float* __restrict__ b2,
                                         const ull* __restrict__ hp, int j) {
    const float* Wp = W2 + j;
    ull acc = 0ull;
#pragma unroll 8
    for (int k = 0; k < HID_; k++) {
        ffma2(acc, pack2(__ldg(Wp)), hp[k]);
        Wp += DOUT;
    }
    float2 s = unpack2(acc);
    float bb = __ldg(b2 + j);
    s.x += bb; s.y += bb;
    return s;
}

template <int DA, int DB>
__device__ __forceinline__ void dot512_dual(
        const float* __restrict__ WA, const float* __restrict__ bA,
        const ull* __restrict__ hpA, int jA, float2& outA,
        const float* __restrict__ WB, const float* __restrict__ bB,
        const ull* __restrict__ hpB, int jB, float2& outB) {
    const float* wa = WA + jA;
    const float* wb = WB + jB;
    ull aA = 0ull, aB = 0ull;
#pragma unroll 4
    for (int k = 0; k < HID_; k++) {
        ffma2(aA, pack2(__ldg(wa)), hpA[k]); wa += DA;
        ffma2(aB, pack2(__ldg(wb)), hpB[k]); wb += DB;
    }
    outA = unpack2(aA); float ba = __ldg(bA + jA); outA.x += ba; outA.y += ba;
    outB = unpack2(aB); float bb = __ldg(bB + jB); outB.x += bb; outB.y += bb;
}

// robust gating + mu/sigma update — expression ordering mirrors the JAX code
__device__ __forceinline__ void gate_update(float xb, float mu, float sig, float gbv,
                                            float t1, float t2, float xblo, float xbhi,
                                            float& xbn, float& mun, float& sgn) {
    float inv_gp  = 1.0f / sig;
    float inv_gp2 = 1.0f / (sig * sig);
    float xmmu = xb - mu;
    float delta1 = gbv * (xmmu + (gbv * 0.5f) * (1.0f + inv_gp));
    float delta2 = 1.0f - inv_gp;
    float delta = delta1 * delta2;
    float eps = t2 * (sig * sig - t2 / t1)
              + xmmu * (xmmu + gbv * (1.0f + inv_gp)
                        + (gbv * gbv * 0.5f) * (1.0f + inv_gp2));
    float d2e2 = delta * delta - eps * eps;
    bool c = ((eps >= delta) && (delta >= 0.0f))
          || ((eps <  delta) && (delta <  0.0f))
          || ((delta < eps)  && (eps  <  0.0f))
          || (((2.0f * t2 * t2 / t1) * eps >= d2e2) && (d2e2 > 0.0f));
    float gamma = c ? sig : 1.0f;
    float dxb = gbv / gamma;
    xbn = dxb;
    float xbc = fminf(fmaxf(dxb, xblo), xbhi);
    float c1 = t1 / t2;
    float c2 = 1.0f / t2;
    mun = c1 * mu + c2 * xbc;
    float dm = xbc - mun;
    sgn = sqrtf(c1 * (sig * sig) + c2 * (dm * dm));
}

// store (and optionally clip + write back) one time-index; prefetch u[t_next]
__device__ __forceinline__ void store_outputs(float* __restrict__ out,
                                              const float* __restrict__ u,
                                              SmemX& sm, int b0, int ti,
                                              int t_next, int tid, bool doclip,
                                              float xlo, float xhi, float xblo,
                                              float xbhi, float ylo, float yhi) {
    float* sxf = reinterpret_cast<float*>(sm.xf);
    float* sxp = reinterpret_cast<float*>(sm.xp);
    float* sxb = reinterpret_cast<float*>(sm.xb);
    {
        int bm = tid >> 6, i = tid & 63;
        int si = (((bm >> 1) * NXF_ + i) << 1) | (bm & 1);
        size_t base = ((size_t)(b0 + bm) * T_ + ti);
        float vf = sxf[si], vp = sxp[si];
        if (doclip) {
            vf = clipf(vf, xlo, xhi); vp = clipf(vp, xlo, xhi);
            sxf[si] = vf; sxp[si] = vp;
        }
        out[OFF_XF + base * NXF_ + i] = vf;
        out[OFF_XP + base * NXF_ + i] = vp;
    }
    if (tid < 256) {
        int bm = tid >> 5, i = tid & 31;
        int si = (((bm >> 1) * NXB_ + i) << 1) | (bm & 1);
        float v = sxb[si];
        if (doclip) { v = clipf(v, xblo, xbhi); sxb[si] = v; }
        out[OFF_XB + ((size_t)(b0 + bm) * T_ + ti) * NXB_ + i] = v;
    }
    if (tid < 128) {
        int bm = tid >> 4, i = tid & 15;
        int si = (((bm >> 1) * NY_ + i) << 1) | (bm & 1);
        float v = reinterpret_cast<float*>(sm.yoh)[si]
                + reinterpret_cast<float*>(sm.yohb)[si];
        if (doclip) v = clipf(v, ylo, yhi);
        out[OFF_Y + ((size_t)(b0 + bm) * T_ + ti) * NY_ + i] = v;
    }
    if (tid >= 384) {   // prefetch u[:, t_next, :] for next iteration
        int tt = tid - 384;
        int bm = tt >> 4, i = tt & 15;
        reinterpret_cast<float*>(sm.uu)[(((bm >> 1) * NU_ + i) << 1) | (bm & 1)] =
            u[((size_t)(b0 + bm) * T_ + t_next) * NU_ + i];
    }
}

// ---------------------------------------------------------------------------
// fused h + h_b: build inputs, fused L1 (8 chains), L2 (128 parallel chains)
// ---------------------------------------------------------------------------
__device__ __forceinline__ void hhb_mlps(SmemX& sm, int tid,
        const float* __restrict__ hW1,  const float* __restrict__ hb1,
        const float* __restrict__ hW2,  const float* __restrict__ hb2_,
        const float* __restrict__ hbW1, const float* __restrict__ hbb1,
        const float* __restrict__ hbW2, const float* __restrict__ hbb2) {
    // build in_h = concat(xp, thh), in_hb = concat(xf, xb)   [k][p]
    if (tid < DIN_H * P) {
        int p = tid / DIN_H, k = tid - p * DIN_H;
        float2 v = (k < NXF_) ? sm.xp[p * NXF_ + k] : sm.thh[p * NTH_ + (k - NXF_)];
        sm.in_h[(k << 2) | p] = v;
    }
    if (tid < DIN_HB * P) {
        int p = tid / DIN_HB, k = tid - p * DIN_HB;
        float2 v = (k < NXF_) ? sm.xf[p * NXF_ + k] : sm.xb[p * NXB_ + (k - NXF_)];
        sm.in_hb[(k << 2) | p] = v;
    }
    __syncthreads();

    // fused L1: thread j owns hidden unit j of h AND hb (8 chains)
    {
        const int j = tid;
        const float* wh = hW1 + j;
        const float* wb = hbW1 + j;
        ull ah0 = 0, ah1 = 0, ah2 = 0, ah3 = 0;
        ull ab0 = 0, ab1 = 0, ab2 = 0, ab3 = 0;
        const ulonglong2* inh = reinterpret_cast<const ulonglong2*>(sm.in_h);
        const ulonglong2* inb = reinterpret_cast<const ulonglong2*>(sm.in_hb);
#pragma unroll 2
        for (int k = 0; k < DIN_H; k++) {
            ull wwh = pack2(__ldg(wh)); wh += HID_;
            ull wwb = pack2(__ldg(wb)); wb += HID_;
            ulonglong2 ha = inh[2 * k], hc = inh[2 * k + 1];
            ulonglong2 ba = inb[2 * k], bc = inb[2 * k + 1];
            ffma2(ah0, wwh, ha.x); ffma2(ah1, wwh, ha.y);
            ffma2(ah2, wwh, hc.x); ffma2(ah3, wwh, hc.y);
            ffma2(ab0, wwb, ba.x); ffma2(ab1, wwb, ba.y);
            ffma2(ab2, wwb, bc.x); ffma2(ab3, wwb, bc.y);
        }
#pragma unroll 4
        for (int k = DIN_H; k < DIN_HB; k++) {
            ull wwb = pack2(__ldg(wb)); wb += HID_;
            ulonglong2 ba = inb[2 * k], bc = inb[2 * k + 1];
            ffma2(ab0, wwb, ba.x); ffma2(ab1, wwb, ba.y);
            ffma2(ab2, wwb, bc.x); ffma2(ab3, wwb, bc.y);
        }
        float bh = __ldg(hb1 + j), bb = __ldg(hbb1 + j);
        sm.hidf [0 * HID_ + j] = tanh2(ah0, bh);
        sm.hidf [1 * HID_ + j] = tanh2(ah1, bh);
        sm.hidf [2 * HID_ + j] = tanh2(ah2, bh);
        sm.hidf [3 * HID_ + j] = tanh2(ah3, bh);
        sm.hidfb[0 * HID_ + j] = tanh2(ab0, bb);
        sm.hidfb[1 * HID_ + j] = tanh2(ab1, bb);
        sm.hidfb[2 * HID_ + j] = tanh2(ab2, bb);
        sm.hidfb[3 * HID_ + j] = tanh2(ab3, bb);
    }
    __syncthreads();

    // fused L2: 64 h-tasks + 64 hb-tasks in parallel
    if (tid < 128) {
        const bool isH = tid < 64;
        const int tA = isH ? tid : tid - 64;
        const int j = tA & 15, p = tA >> 4;
        const ull* hp = reinterpret_cast<const ull*>(isH ? sm.hidf : sm.hidfb)
                      + p * HID_;
        float2 r = dot512<NY_>(isH ? hW2 : hbW2, isH ? hb2_ : hbb2, hp, j);
        (isH ? sm.yoh : sm.yohb)[p * NY_ + j] = r;
    }
    __syncthreads();
}

// ---------------------------------------------------------------------------
// main persistent kernel: one CTA simulates 8 batch rows for all 256 steps
// ---------------------------------------------------------------------------
__global__ void __launch_bounds__(NT, 1)
sim_kernel(const float* __restrict__ xf0, const float* __restrict__ xb0,
           const float* __restrict__ u,   const float* __restrict__ thfg,
           const float* __restrict__ thhg,
           const float* __restrict__ fW1,  const float* __restrict__ fb1,
           const float* __restrict__ fW2,  const float* __restrict__ fb2_,
           const float* __restrict__ fbW1, const float* __restrict__ fbb1,
           const float* __restrict__ fbW2, const float* __restrict__ fbb2,
           const float* __restrict__ gbW1, const float* __restrict__ gbb1,
           const float* __restrict__ gbW2, const float* __restrict__ gbb2,
           const float* __restrict__ hW1,  const float* __restrict__ hb1,
           const float* __restrict__ hW2,  const float* __restrict__ hb2_,
           const float* __restrict__ hbW1, const float* __restrict__ hbb1,
           const float* __restrict__ hbW2, const float* __restrict__ hbb2,
           const float* __restrict__ pxlo, const float* __restrict__ pxhi,
           const float* __restrict__ pxblo,const float* __restrict__ pxbhi,
           const float* __restrict__ pylo, const float* __restrict__ pyhi,
           float* __restrict__ out) {
    extern __shared__ __align__(16) char dynraw[];
    SmemX& sm = *reinterpret_cast<SmemX*>(dynraw);

    const int tid = threadIdx.x;
    const int b0  = blockIdx.x * BM;
    const float xlo = pxlo[0], xhi = pxhi[0];
    const float xblo = pxblo[0], xbhi = pxbhi[0];
    const float ylo = pylo[0], yhi = pyhi[0];

    // ---- prologue: load initial state (pair-packed) + u_0 ----
    {
        int bm = tid >> 6, i = tid & 63;
        float v = xf0[(b0 + bm) * NXF_ + i];
        int si = (((bm >> 1) * NXF_ + i) << 1) | (bm & 1);
        reinterpret_cast<float*>(sm.xf)[si] = v;
        reinterpret_cast<float*>(sm.xp)[si] = v;
    }
    if (tid < 256) {
        int bm = tid >> 5, i = tid & 31;
        float v = xb0[(b0 + bm) * NXB_ + i];
        int si = (((bm >> 1) * NXB_ + i) << 1) | (bm & 1);
        reinterpret_cast<float*>(sm.xb)[si]  = v;
        reinterpret_cast<float*>(sm.mu)[si]  = 0.0f;
        reinterpret_cast<float*>(sm.sig)[si] = 1.0f;
    }
    if (tid < 64) {
        int bm = tid >> 3, i = tid & 7;
        int si = (((bm >> 1) * NTH_ + i) << 1) | (bm & 1);
        reinterpret_cast<float*>(sm.thf)[si] = thfg[(b0 + bm) * NTH_ + i];
        reinterpret_cast<float*>(sm.thh)[si] = thhg[(b0 + bm) * NTH_ + i];
    }
    if (tid >= 128 && tid < 256) {
        int tt = tid - 128;
        int bm = tt >> 4, i = tt & 15;
        reinterpret_cast<float*>(sm.uu)[(((bm >> 1) * NU_ + i) << 1) | (bm & 1)] =
            u[((size_t)(b0 + bm) * T_ + 0) * NU_ + i];
    }
    __syncthreads();

    // ---- y0 = h(x_f_0) + h_b(x_f_0, x_b_0), stored (unclipped) at t=0 ----
    hhb_mlps(sm, tid, hW1, hb1, hW2, hb2_, hbW1, hbb1, hbW2, hbb2);
    store_outputs(out, u, sm, b0, 0, 0, tid, false,
                  xlo, xhi, xblo, xbhi, ylo, yhi);
    __syncthreads();

    // ---- main recurrence: updates for t = 0..254, stored at t+1 ----
    for (int t = 0; t < T_ - 1; t++) {
        const float tf = (float)t;

        // phase 1: build in_f = (xp,u,thf), in_fb = (xp,xb,u)   [k][p]
        if (tid < DIN_F * P) {
            int p = tid / DIN_F, k = tid - p * DIN_F;
            float2 v;
            if (k < NXF_)            v = sm.xp[p * NXF_ + k];
            else if (k < NXF_ + NU_) v = sm.uu[p * NU_ + (k - NXF_)];
            else                     v = sm.thf[p * NTH_ + (k - NXF_ - NU_)];
            sm.in_f[(k << 2) | p] = v;
        }
        if (tid < DIN_FB * P) {
            int p = tid / DIN_FB, k = tid - p * DIN_FB;
            float2 v;
            if (k < NXF_)             v = sm.xp[p * NXF_ + k];
            else if (k < NXF_ + NXB_) v = sm.xb[p * NXB_ + (k - NXF_)];
            else                      v = sm.uu[p * NU_ + (k - NXF_ - NXB_)];
            sm.in_fb[(k << 2) | p] = v;
        }
        __syncthreads();

        // phase 2: fused L1 of f + fb + gb (12 chains per thread)
        {
            const int j = tid;
            const float* wf = fW1 + j;
            const float* wb = fbW1 + j;
            const float* wg = gbW1 + j;
            ull af0 = 0, af1 = 0, af2 = 0, af3 = 0;
            ull ab0 = 0, ab1 = 0, ab2 = 0, ab3 = 0;
            ull ag0 = 0, ag1 = 0, ag2 = 0, ag3 = 0;
            const ulonglong2* inf = reinterpret_cast<const ulonglong2*>(sm.in_f);
            const ulonglong2* inb = reinterpret_cast<const ulonglong2*>(sm.in_fb);
#pragma unroll 2
            for (int k = 0; k < DIN_F; k++) {
                ull wwf = pack2(__ldg(wf)); wf += HID_;
                ull wwb = pack2(__ldg(wb)); wb += HID_;
                ull wwg = pack2(__ldg(wg)); wg += HID_;
                ulonglong2 fa = inf[2 * k], fc = inf[2 * k + 1];
                ulonglong2 ba = inb[2 * k], bc = inb[2 * k + 1];
                ffma2(af0, wwf, fa.x); ffma2(af1, wwf, fa.y);
                ffma2(af2, wwf, fc.x); ffma2(af3, wwf, fc.y);
                ffma2(ab0, wwb, ba.x); ffma2(ab1, wwb, ba.y);
                ffma2(ab2, wwb, bc.x); ffma2(ab3, wwb, bc.y);
                ffma2(ag0, wwg, ba.x); ffma2(ag1, wwg, ba.y);
                ffma2(ag2, wwg, bc.x); ffma2(ag3, wwg, bc.y);
            }
#pragma unroll 2
            for (int k = DIN_F; k < DIN_FB; k++) {
                ull wwb = pack2(__ldg(wb)); wb += HID_;
                ull wwg = pack2(__ldg(wg)); wg += HID_;
                ulonglong2 ba = inb[2 * k], bc = inb[2 * k + 1];
                ffma2(ab0, wwb, ba.x); ffma2(ab1, wwb, ba.y);
                ffma2(ab2, wwb, bc.x); ffma2(ab3, wwb, bc.y);
                ffma2(ag0, wwg, ba.x); ffma2(ag1, wwg, ba.y);
                ffma2(ag2, wwg, bc.x); ffma2(ag3, wwg, bc.y);
            }
            float bf = __ldg(fb1 + j), bb = __ldg(fbb1 + j), bg = __ldg(gbb1 + j);
            sm.hidf [0 * HID_ + j] = tanh2(af0, bf);
            sm.hidf [1 * HID_ + j] = tanh2(af1, bf);
            sm.hidf [2 * HID_ + j] = tanh2(af2, bf);
            sm.hidf [3 * HID_ + j] = tanh2(af3, bf);
            sm.hidfb[0 * HID_ + j] = tanh2(ab0, bb);
            sm.hidfb[1 * HID_ + j] = tanh2(ab1, bb);
            sm.hidfb[2 * HID_ + j] = tanh2(ab2, bb);
            sm.hidfb[3 * HID_ + j] = tanh2(ab3, bb);
            sm.hidgb[0 * HID_ + j] = tanh2(ag0, bg);
            sm.hidgb[1 * HID_ + j] = tanh2(ag1, bg);
            sm.hidgb[2 * HID_ + j] = tanh2(ag2, bg);
            sm.hidgb[3 * HID_ + j] = tanh2(ag3, bg);
        }
        __syncthreads();

        // phase 3: fused L2 of f (256 tasks) + fb (256) + gb (128)
        {
            const bool isF = tid < 256;
            const int tA = isF ? tid : tid - 256;
            const int jA = tA & 63, pA = tA >> 6;
            const float* WA = isF ? fW2 : fbW2;
            const float* bA = isF ? fb2_ : fbb2;
            const ull* hpA = reinterpret_cast<const ull*>(isF ? sm.hidf : sm.hidfb)
                           + pA * HID_;
            float2* outA = isF ? sm.fo : sm.fbo;
            if (tid < 128) {
                const int jB = tid & 31, pB = tid >> 5;
                const ull* hpB = reinterpret_cast<const ull*>(sm.hidgb) + pB * HID_;
                float2 rA, rB;
                dot512_dual<NXF_, NXB_>(WA, bA, hpA, jA, rA,
                                        gbW2, gbb2, hpB, jB, rB);
                outA[pA * NXF_ + jA] = rA;
                sm.gbo[pB * NXB_ + jB] = rB;
            } else {
                outA[pA * NXF_ + jA] = dot512<NXF_>(WA, bA, hpA, jA);
            }
        }
        __syncthreads();

        // phase 4: elementwise state update (unclipped kept for h / h_b)
        if (tid < 128) {
            int q = tid;
            float2 xb2 = sm.xb[q], mu2 = sm.mu[q], sg2 = sm.sig[q], gb2 = sm.gbo[q];
            float xbn, mun, sgn;
            gate_update(xb2.x, mu2.x, sg2.x, gb2.x, tf + 1.0f, tf + 2.0f,
                        xblo, xbhi, xbn, mun, sgn);
            xb2.x = xbn; mu2.x = mun; sg2.x = sgn;
            gate_update(xb2.y, mu2.y, sg2.y, gb2.y, tf + 1.0f, tf + 2.0f,
                        xblo, xbhi, xbn, mun, sgn);
            xb2.y = xbn; mu2.y = mun; sg2.y = sgn;
            sm.xb[q] = xb2; sm.mu[q] = mu2; sm.sig[q] = sg2;
        } else if (tid < 384) {
            int q = tid - 128;
            float2 xp2 = sm.xp[q], xf2 = sm.xf[q], f2 = sm.fo[q], fb2 = sm.fbo[q];
            float dfx = f2.x + fb2.x, dfy = f2.y + fb2.y;
            sm.xp[q] = make_float2(xp2.x + f2.x, xp2.y + f2.y);
            sm.xf[q] = make_float2(xf2.x + dfx, xf2.y + dfy);
        }
        __syncthreads();

        // phases 5-7: y_n = h(xp_n) + h_b(xf_n, xb_n)   (pre-clip values)
        hhb_mlps(sm, tid, hW1, hb1, hW2, hb2_, hbW1, hbb1, hbW2, hbb2);

        // phase 8: clip states (write-back) + store at t+1 + prefetch u[t+1]
        store_outputs(out, u, sm, b0, t + 1, t + 1, tid, true,
                      xlo, xhi, xblo, xbhi, ylo, yhi);
        __syncthreads();
    }
}

// ---------------------------------------------------------------------------
extern "C" void kernel_launch(void* const* d_in, const int* in_sizes, int n_in,
                              void* d_out, int out_size) {
    (void)in_sizes; (void)n_in; (void)out_size;
    const float* a0  = (const float*)d_in[0];   // x_f_0
    const float* a1  = (const float*)d_in[1];   // x_b_0
    const float* a2  = (const float*)d_in[2];   // u
    const float* a3  = (const float*)d_in[3];   // theta_f
    const float* a4  = (const float*)d_in[4];   // theta_h
    const float* a5  = (const float*)d_in[5];   // f_W1
    const float* a6  = (const float*)d_in[6];
    const float* a7  = (const float*)d_in[7];
    const float* a8  = (const float*)d_in[8];
    const float* a9  = (const float*)d_in[9];   // fb_W1
    const float* a10 = (const float*)d_in[10];
    const float* a11 = (const float*)d_in[11];
    const float* a12 = (const float*)d_in[12];
    const float* a13 = (const float*)d_in[13];  // gb_W1
    const float* a14 = (const float*)d_in[14];
    const float* a15 = (const float*)d_in[15];
    const float* a16 = (const float*)d_in[16];
    const float* a17 = (const float*)d_in[17];  // h_W1
    const float* a18 = (const float*)d_in[18];
    const float* a19 = (const float*)d_in[19];
    const float* a20 = (const float*)d_in[20];
    const float* a21 = (const float*)d_in[21];  // hb_W1
    const float* a22 = (const float*)d_in[22];
    const float* a23 = (const float*)d_in[23];
    const float* a24 = (const float*)d_in[24];
    const float* a25 = (const float*)d_in[25];  // x_lo
    const float* a26 = (const float*)d_in[26];  // x_hi
    const float* a27 = (const float*)d_in[27];  // xb_lo
    const float* a28 = (const float*)d_in[28];  // xb_hi
    const float* a29 = (const float*)d_in[29];  // y_lo
    const float* a30 = (const float*)d_in[30];  // y_hi

    cudaFuncSetAttribute(sim_kernel,
                         cudaFuncAttributeMaxDynamicSharedMemorySize,
                         (int)sizeof(SmemX));

    sim_kernel<<<B_ / BM, NT, sizeof(SmemX)>>>(a0, a1, a2, a3, a4,
                                a5, a6, a7, a8,
                                a9, a10, a11, a12,
                                a13, a14, a15, a16,
                                a17, a18, a19, a20,
                                a21, a22, a23, a24,
                                a25, a26, a27, a28, a29, a30,
                                (float*)d_out);
}